// round 17
// baseline (speedup 1.0000x reference)
#include <cuda_runtime.h>
#include <cuda_fp16.h>
#include <cstdint>
#include <math.h>

#define B_SZ   65536
#define IN_D   512
#define H_DIM  512
#define H3     1536
#define NHEAD  8
#define HDIM   64
#define LN_EPS 1e-5f

#define GK     512
#define NCH    8
#define GBK    64

// GEMM1 (256x128, 512 thr)
#define G1_BM  256
#define G1_BN  128
#define G1_STA 32768
#define G1_STAGE 49152
#define G1_SMEM (3 * G1_STAGE)

// GEMM2 + LN + attention: A-resident, 96 rows (32 batches), all 8 heads/CTA
#define G2_THREADS 384
#define G2_ACH   12288                     // one 96x64 fp16 chunk tile
#define G2_ARES  (8 * G2_ACH)              // 98304
#define G2_STB   24576                     // 192x64 fp16 B stage
#define G2_BOFF  G2_ARES
#define G2_EOFF  (G2_ARES + 3 * G2_STB)    // 172032 epilogue staging (96x192 f16)
#define G2_SOFF  (G2_EOFF + 96 * 192 * 2)  // 208896 stats
#define G2_SMEM  (G2_SOFF + 256)           // 209152

// GEMM3+gumbel (96x128, 256 thr)
#define G3_BM  96
#define G3_BN  128
#define G3_STA 12288
#define G3_STB 16384
#define G3_STAGE (G3_STA + G3_STB)
#define G3_SMEM (3 * G3_STAGE)

#define SW128(o) ((o) ^ (((o) >> 3) & 0x70))

// ---------------------------------------------------------------------------
// Scratch
// ---------------------------------------------------------------------------
__device__ __half g_a  [(size_t)B_SZ * H3];          // h (raw, pre-LN)
__device__ __half g_ctx[(size_t)B_SZ * 3 * H_DIM];   // ctx [3B,512]
__device__ __half g_x16[(size_t)B_SZ * IN_D];
__device__ __half g_wfc [(size_t)H3 * IN_D];
__device__ __half g_wqkv[(size_t)H3 * H_DIM];        // permuted rows
__device__ float  g_bqkv[H3];
__device__ __half g_wo  [(size_t)H_DIM * H_DIM];

// ---------------------------------------------------------------------------
// helpers
// ---------------------------------------------------------------------------
static __device__ __forceinline__ uint32_t smem_u32(const void* p) {
    uint32_t a;
    asm("{ .reg .u64 t; cvta.to.shared.u64 t, %1; cvt.u32.u64 %0, t; }"
        : "=r"(a) : "l"(p));
    return a;
}

static __device__ __forceinline__ void cp16(uint32_t saddr, const void* g) {
    asm volatile("cp.async.cg.shared.global [%0], [%1], 16;"
                 :: "r"(saddr), "l"(g));
}
#define CP_COMMIT() asm volatile("cp.async.commit_group;" ::: "memory")
#define CP_WAIT(n)  asm volatile("cp.async.wait_group %0;" :: "n"(n) : "memory")

static __device__ __forceinline__ void ldsm_x4(uint32_t* r, uint32_t addr) {
    asm volatile("ldmatrix.sync.aligned.m8n8.x4.shared.b16 {%0,%1,%2,%3}, [%4];"
                 : "=r"(r[0]), "=r"(r[1]), "=r"(r[2]), "=r"(r[3]) : "r"(addr));
}

static __device__ __forceinline__ void mma16816(float* c, const uint32_t* a,
                                                const uint32_t* b) {
    asm volatile(
        "mma.sync.aligned.m16n8k16.row.col.f32.f16.f16.f32 "
        "{%0,%1,%2,%3}, {%4,%5,%6,%7}, {%8,%9}, {%0,%1,%2,%3};"
        : "+f"(c[0]), "+f"(c[1]), "+f"(c[2]), "+f"(c[3])
        : "r"(a[0]), "r"(a[1]), "r"(a[2]), "r"(a[3]), "r"(b[0]), "r"(b[1]));
}

// ---------------------------------------------------------------------------
// GEMM1: fp16 out, 256x128, 512 threads (h = x @ Wfc^T + b, NO ln/relu)
// ---------------------------------------------------------------------------
__global__ __launch_bounds__(512, 1) void gemm_f16(
    const __half* __restrict__ A, const __half* __restrict__ B,
    const float* __restrict__ bias, __half* __restrict__ C, int N)
{
    extern __shared__ char smem[];
    const uint32_t sbase = smem_u32(smem);
    const int tid  = threadIdx.x;
    const int lane = tid & 31;
    const int warp = tid >> 5;
    const int wm   = warp >> 1;
    const int wn   = warp & 1;
    const int m0 = blockIdx.y * G1_BM;
    const int n0 = blockIdx.x * G1_BN;

    const int arow[4] = { (0 * 512 + tid) >> 3, (1 * 512 + tid) >> 3,
                          (2 * 512 + tid) >> 3, (3 * 512 + tid) >> 3 };
    const int brow[2] = { (0 * 512 + tid) >> 3, (1 * 512 + tid) >> 3 };
    const int unit = tid & 7;

    float acc[2][8][4];
    #pragma unroll
    for (int mf = 0; mf < 2; mf++)
        #pragma unroll
        for (int nf = 0; nf < 8; nf++)
            #pragma unroll
            for (int i = 0; i < 4; i++) acc[mf][nf][i] = 0.0f;

    const uint32_t aRow = (uint32_t)(wm * 32 + (lane & 15));
    const uint32_t aCol = (uint32_t)(lane >> 4) * 16;
    const uint32_t bRow = (uint32_t)(wn * 64 + ((lane >> 4) & 1) * 8 + (lane & 7));
    const uint32_t bCol = (uint32_t)((lane >> 3) & 1) * 16;

    auto load_chunk = [&](int ch, int stg) {
        const uint32_t sb = sbase + (uint32_t)stg * G1_STAGE;
        const int kc = ch * GBK;
        #pragma unroll
        for (int i = 0; i < 4; i++) {
            const uint32_t so = SW128((uint32_t)arow[i] * 128 + unit * 16);
            cp16(sb + so, A + (size_t)(m0 + arow[i]) * GK + kc + unit * 8);
        }
        #pragma unroll
        for (int i = 0; i < 2; i++) {
            const uint32_t so = SW128((uint32_t)brow[i] * 128 + unit * 16);
            cp16(sb + G1_STA + so, B + (size_t)(n0 + brow[i]) * GK + kc + unit * 8);
        }
    };

    load_chunk(0, 0); CP_COMMIT();
    load_chunk(1, 1); CP_COMMIT();

    for (int ch = 0; ch < NCH; ch++) {
        if (ch < NCH - 1) { CP_WAIT(1); } else { CP_WAIT(0); }
        __syncthreads();
        if (ch + 2 < NCH) { load_chunk(ch + 2, (ch + 2) % 3); CP_COMMIT(); }

        const uint32_t sb = sbase + (uint32_t)(ch % 3) * G1_STAGE;
        #pragma unroll
        for (int kk = 0; kk < 4; kk++) {
            const uint32_t kb = (uint32_t)kk * 32;
            uint32_t af[2][4], bf4[4][4];
            #pragma unroll
            for (int mf = 0; mf < 2; mf++)
                ldsm_x4(af[mf], sb + SW128((aRow + mf * 16) * 128 + kb + aCol));
            #pragma unroll
            for (int p = 0; p < 4; p++)
                ldsm_x4(bf4[p], sb + G1_STA + SW128((bRow + p * 16) * 128 + kb + bCol));
            #pragma unroll
            for (int mf = 0; mf < 2; mf++)
                #pragma unroll
                for (int nf = 0; nf < 8; nf++)
                    mma16816(acc[mf][nf], af[mf], &bf4[nf >> 1][(nf & 1) * 2]);
        }
    }

    const int tq = lane & 3, qd = lane >> 2;
    #pragma unroll
    for (int mf = 0; mf < 2; mf++) {
        #pragma unroll
        for (int nf = 0; nf < 8; nf++) {
            const int col = n0 + wn * 64 + nf * 8 + tq * 2;
            const float b0 = bias[col], b1 = bias[col + 1];
            #pragma unroll
            for (int h = 0; h < 2; h++) {
                const int row = m0 + wm * 32 + mf * 16 + qd + h * 8;
                __half2 o = __halves2half2(
                    __float2half_rn(acc[mf][nf][h * 2 + 0] + b0),
                    __float2half_rn(acc[mf][nf][h * 2 + 1] + b1));
                *reinterpret_cast<__half2*>(C + (size_t)row * N + col) = o;
            }
        }
    }
}

// ---------------------------------------------------------------------------
// GEMM2 fused: LN+ReLU prologue (A resident) + qkv GEMM (all 8 heads) +
// attention epilogue. A = h [3B,512] raw; B = Wqkv_perm; out ctx [3B,512].
// 384 threads, 12 warps = 2(M:48) x 6(N:32); CTA = 96 rows = 32 batches.
// ---------------------------------------------------------------------------
__global__ __launch_bounds__(G2_THREADS, 1) void gemm_ln_qkv_attn(
    const __half* __restrict__ A, const __half* __restrict__ B,
    const float* __restrict__ bias, const float* __restrict__ lng,
    const float* __restrict__ lnb, __half* __restrict__ ctx)
{
    extern __shared__ char smem[];
    const uint32_t sbase = smem_u32(smem);
    const int tid  = threadIdx.x;
    const int lane = tid & 31;
    const int warp = tid >> 5;                 // 0..11
    const int wm   = warp / 6;                 // 0..1 -> M offset wm*48
    const int wn   = warp % 6;                 // 0..5 -> N offset wn*32
    const int m0   = blockIdx.x * 96;
    const int unit = tid & 7;

    // ---- A resident load (one cp.async group) ----
    #pragma unroll
    for (int i = 0; i < 16; i++) {
        const int slot = i * G2_THREADS + tid;     // 0..6143
        const int ch = slot / 768;
        const int rem = slot - ch * 768;
        const int r = rem >> 3, u = rem & 7;
        cp16(sbase + ch * G2_ACH + SW128((uint32_t)r * 128 + u * 16),
             A + (size_t)(m0 + r) * GK + ch * 64 + u * 8);
    }
    CP_COMMIT();

    auto loadB = [&](int step, int stg) {       // step = head*8 + ch
        const int hd = step >> 3, ch = step & 7;
        const uint32_t sb = sbase + G2_BOFF + (uint32_t)stg * G2_STB;
        #pragma unroll
        for (int i = 0; i < 4; i++) {
            const int r = (i * G2_THREADS + tid) >> 3;   // 0..191
            cp16(sb + SW128((uint32_t)r * 128 + unit * 16),
                 B + (size_t)(hd * 192 + r) * GK + ch * 64 + unit * 8);
        }
    };
    loadB(0, 0); CP_COMMIT();
    loadB(1, 1); CP_COMMIT();

    CP_WAIT(2);          // A resident complete
    __syncthreads();

    // ---- LN stats: warp per batch (bb = warp, warp+12, warp+24) ----
    float* sStats = reinterpret_cast<float*>(smem + G2_SOFF);
    for (int bb = warp; bb < 32; bb += 12) {
        float s = 0.0f, ss = 0.0f;
        #pragma unroll
        for (int ch = 0; ch < 8; ch++)
            #pragma unroll
            for (int t = 0; t < 3; t++) {
                const int r = 3 * bb + t;
                float2 f = __half22float2(*reinterpret_cast<const __half2*>(
                    smem + ch * G2_ACH + r * 128 + lane * 4));
                s += f.x + f.y;
                ss += f.x * f.x + f.y * f.y;
            }
        #pragma unroll
        for (int of = 16; of > 0; of >>= 1) {
            s  += __shfl_xor_sync(0xffffffffu, s, of);
            ss += __shfl_xor_sync(0xffffffffu, ss, of);
        }
        if (lane == 0) {
            const float mean = s * (1.0f / H3);
            const float var  = ss * (1.0f / H3) - mean * mean;
            sStats[2 * bb]     = mean;
            sStats[2 * bb + 1] = rsqrtf(var + LN_EPS);
        }
    }
    __syncthreads();

    // ---- rescale + affine + ReLU in place ----
    #pragma unroll
    for (int i = 0; i < 16; i++) {
        const int slot = i * G2_THREADS + tid;
        const int ch = slot / 768;
        const int rem = slot - ch * 768;
        const int r = rem >> 3, u = rem & 7;
        const int t = r % 3;
        const int col0 = t * 512 + ch * 64 + u * 8;
        const float mean = sStats[2 * (r / 3)];
        const float rstd = sStats[2 * (r / 3) + 1];
        __half2* p = reinterpret_cast<__half2*>(
            smem + ch * G2_ACH + SW128((uint32_t)r * 128 + u * 16));
        #pragma unroll
        for (int j = 0; j < 4; j++) {
            float2 f = __half22float2(p[j]);
            const int c = col0 + 2 * j;
            float y0 = (f.x - mean) * rstd * lng[c]     + lnb[c];
            float y1 = (f.y - mean) * rstd * lng[c + 1] + lnb[c + 1];
            p[j] = __halves2half2(__float2half_rn(fmaxf(y0, 0.0f)),
                                  __float2half_rn(fmaxf(y1, 0.0f)));
        }
    }
    __syncthreads();

    // ---- mainloop over 64 steps (8 heads x 8 K-chunks) ----
    const uint32_t aRow = (uint32_t)(wm * 48 + (lane & 15));
    const uint32_t aCol = (uint32_t)(lane >> 4) * 16;
    const uint32_t bRow = (uint32_t)(wn * 32 + ((lane >> 4) & 1) * 8 + (lane & 7));
    const uint32_t bCol = (uint32_t)((lane >> 3) & 1) * 16;
    const int tq = lane & 3, qd = lane >> 2;

    float acc[3][4][4];
    #pragma unroll
    for (int mf = 0; mf < 3; mf++)
        #pragma unroll
        for (int nf = 0; nf < 4; nf++)
            #pragma unroll
            for (int i = 0; i < 4; i++) acc[mf][nf][i] = 0.0f;

    for (int s = 0; s < 64; s++) {
        if (s < 63) { CP_WAIT(1); } else { CP_WAIT(0); }
        __syncthreads();
        if (s + 2 < 64) { loadB(s + 2, (s + 2) % 3); CP_COMMIT(); }

        const uint32_t sB = sbase + G2_BOFF + (uint32_t)(s % 3) * G2_STB;
        const uint32_t sA = sbase + (uint32_t)(s & 7) * G2_ACH;

        #pragma unroll
        for (int kk = 0; kk < 4; kk++) {
            const uint32_t kb = (uint32_t)kk * 32;
            uint32_t af[3][4], bf2[2][4];
            #pragma unroll
            for (int mf = 0; mf < 3; mf++)
                ldsm_x4(af[mf], sA + SW128((aRow + mf * 16) * 128 + kb + aCol));
            #pragma unroll
            for (int p = 0; p < 2; p++)
                ldsm_x4(bf2[p], sB + SW128((bRow + p * 16) * 128 + kb + bCol));
            #pragma unroll
            for (int mf = 0; mf < 3; mf++)
                #pragma unroll
                for (int nf = 0; nf < 4; nf++)
                    mma16816(acc[mf][nf], af[mf], &bf2[nf >> 1][(nf & 1) * 2]);
        }

        if ((s & 7) == 7) {
            const int head = s >> 3;
            // stage qkv tile (96x192 fp16) + bias
            __half* sE = reinterpret_cast<__half*>(smem + G2_EOFF);
            #pragma unroll
            for (int mf = 0; mf < 3; mf++) {
                #pragma unroll
                for (int nf = 0; nf < 4; nf++) {
                    const int col_l = wn * 32 + nf * 8 + tq * 2;
                    const float b0 = bias[head * 192 + col_l];
                    const float b1 = bias[head * 192 + col_l + 1];
                    #pragma unroll
                    for (int h = 0; h < 2; h++) {
                        const int row_l = wm * 48 + mf * 16 + qd + h * 8;
                        *reinterpret_cast<__half2*>(sE + row_l * 192 + col_l) =
                            __halves2half2(
                                __float2half_rn(acc[mf][nf][h * 2 + 0] + b0),
                                __float2half_rn(acc[mf][nf][h * 2 + 1] + b1));
                        acc[mf][nf][h * 2 + 0] = 0.0f;
                        acc[mf][nf][h * 2 + 1] = 0.0f;
                    }
                }
            }
            __syncthreads();

            // attention: warp handles batches warp, warp+12, warp+24 (<32)
            for (int bb = warp; bb < 32; bb += 12) {
                const size_t b = (size_t)blockIdx.x * 32 + bb;
                const __half* rb = sE + (3 * bb) * 192;
                float2 q[3], k[3], v[3];
                #pragma unroll
                for (int t = 0; t < 3; t++) {
                    const __half* r = rb + t * 192;
                    q[t] = __half22float2(*reinterpret_cast<const __half2*>(r + 2 * lane));
                    k[t] = __half22float2(*reinterpret_cast<const __half2*>(r + 64 + 2 * lane));
                    v[t] = __half22float2(*reinterpret_cast<const __half2*>(r + 128 + 2 * lane));
                }
                float sc[3][3];
                #pragma unroll
                for (int i = 0; i < 3; i++)
                    #pragma unroll
                    for (int jj = 0; jj < 3; jj++)
                        sc[i][jj] = q[i].x * k[jj].x + q[i].y * k[jj].y;
                #pragma unroll
                for (int of = 16; of > 0; of >>= 1)
                    #pragma unroll
                    for (int i = 0; i < 3; i++)
                        #pragma unroll
                        for (int jj = 0; jj < 3; jj++)
                            sc[i][jj] += __shfl_xor_sync(0xffffffffu, sc[i][jj], of);
                float p[3][3];
                #pragma unroll
                for (int i = 0; i < 3; i++) {
                    float a0 = sc[i][0] * 0.125f, a1 = sc[i][1] * 0.125f, a2 = sc[i][2] * 0.125f;
                    float m = fmaxf(a0, fmaxf(a1, a2));
                    float e0 = expf(a0 - m), e1 = expf(a1 - m), e2 = expf(a2 - m);
                    float inv = 1.0f / (e0 + e1 + e2);
                    p[i][0] = e0 * inv; p[i][1] = e1 * inv; p[i][2] = e2 * inv;
                }
                #pragma unroll
                for (int i = 0; i < 3; i++) {
                    float cx = p[i][0] * v[0].x + p[i][1] * v[1].x + p[i][2] * v[2].x;
                    float cy = p[i][0] * v[0].y + p[i][1] * v[1].y + p[i][2] * v[2].y;
                    *reinterpret_cast<__half2*>(
                        ctx + (b * 3 + i) * H_DIM + head * HDIM + 2 * lane) =
                        __halves2half2(__float2half_rn(cx), __float2half_rn(cy));
                }
            }
        }
    }
}

// ---------------------------------------------------------------------------
// GEMM3 + fused gumbel softmax (unchanged from R15)
// ---------------------------------------------------------------------------
__global__ __launch_bounds__(256, 2) void gemm_out_gumbel(
    const __half* __restrict__ A, const __half* __restrict__ B,
    const float* __restrict__ bias, const float* __restrict__ gum,
    float* __restrict__ out)
{
    extern __shared__ char smem[];
    const uint32_t sbase = smem_u32(smem);
    const int tid  = threadIdx.x;
    const int lane = tid & 31;
    const int warp = tid >> 5;
    const int wm   = warp >> 2;
    const int wn   = warp & 3;
    const int m0 = blockIdx.y * G3_BM;
    const int n0 = blockIdx.x * G3_BN;

    int arow[3], brow[4];
    #pragma unroll
    for (int i = 0; i < 3; i++) arow[i] = (i * 256 + tid) >> 3;
    #pragma unroll
    for (int i = 0; i < 4; i++) brow[i] = (i * 256 + tid) >> 3;
    const int unit = tid & 7;

    float acc[3][4][4];
    #pragma unroll
    for (int mf = 0; mf < 3; mf++)
        #pragma unroll
        for (int nf = 0; nf < 4; nf++)
            #pragma unroll
            for (int i = 0; i < 4; i++) acc[mf][nf][i] = 0.0f;

    const uint32_t aRow = (uint32_t)(wm * 48 + (lane & 15));
    const uint32_t aCol = (uint32_t)(lane >> 4) * 16;
    const uint32_t bRow = (uint32_t)(wn * 32 + ((lane >> 4) & 1) * 8 + (lane & 7));
    const uint32_t bCol = (uint32_t)((lane >> 3) & 1) * 16;

    auto load_chunk = [&](int ch, int stg) {
        const uint32_t sb = sbase + (uint32_t)stg * G3_STAGE;
        const int kc = ch * GBK;
        #pragma unroll
        for (int i = 0; i < 3; i++) {
            const uint32_t so = SW128((uint32_t)arow[i] * 128 + unit * 16);
            cp16(sb + so, A + (size_t)(m0 + arow[i]) * GK + kc + unit * 8);
        }
        #pragma unroll
        for (int i = 0; i < 4; i++) {
            const uint32_t so = SW128((uint32_t)brow[i] * 128 + unit * 16);
            cp16(sb + G3_STA + so, B + (size_t)(n0 + brow[i]) * GK + kc + unit * 8);
        }
    };

    load_chunk(0, 0); CP_COMMIT();
    load_chunk(1, 1); CP_COMMIT();

    for (int ch = 0; ch < NCH; ch++) {
        if (ch < NCH - 1) { CP_WAIT(1); } else { CP_WAIT(0); }
        __syncthreads();
        if (ch + 2 < NCH) { load_chunk(ch + 2, (ch + 2) % 3); CP_COMMIT(); }

        const uint32_t sb = sbase + (uint32_t)(ch % 3) * G3_STAGE;
        #pragma unroll
        for (int kk = 0; kk < 4; kk++) {
            const uint32_t kb = (uint32_t)kk * 32;
            uint32_t af[3][4], bf2[2][4];
            #pragma unroll
            for (int mf = 0; mf < 3; mf++)
                ldsm_x4(af[mf], sb + SW128((aRow + mf * 16) * 128 + kb + aCol));
            #pragma unroll
            for (int p = 0; p < 2; p++)
                ldsm_x4(bf2[p], sb + G3_STA + SW128((bRow + p * 16) * 128 + kb + bCol));
            #pragma unroll
            for (int mf = 0; mf < 3; mf++)
                #pragma unroll
                for (int nf = 0; nf < 4; nf++)
                    mma16816(acc[mf][nf], af[mf], &bf2[nf >> 1][(nf & 1) * 2]);
        }
    }

    __syncthreads();
    float* sF = reinterpret_cast<float*>(smem);
    const int tq = lane & 3, qd = lane >> 2;
    #pragma unroll
    for (int mf = 0; mf < 3; mf++) {
        #pragma unroll
        for (int nf = 0; nf < 4; nf++) {
            const int col_l = wn * 32 + nf * 8 + tq * 2;
            const float b0 = bias[n0 + col_l], b1 = bias[n0 + col_l + 1];
            #pragma unroll
            for (int h = 0; h < 2; h++) {
                const int row_l = wm * 48 + mf * 16 + qd + h * 8;
                float2 o;
                o.x = acc[mf][nf][h * 2 + 0] + b0;
                o.y = acc[mf][nf][h * 2 + 1] + b1;
                *reinterpret_cast<float2*>(sF + row_l * 132 + col_l) = o;
            }
        }
    }
    __syncthreads();

    #pragma unroll
    for (int it = 0; it < 16; it++) {
        const int idx = it * 256 + tid;
        const int bl = idx >> 7;
        const int c  = idx & 127;
        const size_t b = (size_t)blockIdx.y * 32 + bl;
        const int col = n0 + c;

        const float l0 = sF[(3 * bl + 0) * 132 + c] + gum[b * H3 + col];
        const float l1 = sF[(3 * bl + 1) * 132 + c] + gum[b * H3 + 512 + col];
        const float l2 = sF[(3 * bl + 2) * 132 + c] + gum[b * H3 + 1024 + col];

        const float m  = fmaxf(l0, fmaxf(l1, l2));
        const float e0 = expf(l0 - m), e1 = expf(l1 - m), e2 = expf(l2 - m);
        const float r  = 1.0f / (e0 + e1 + e2);

        out[b * 512 + col]                          = e0 * r;
        out[(size_t)B_SZ * 512 + b * 512 + col]     = e1 * r;
        out[(size_t)2 * B_SZ * 512 + b * 512 + col] = e2 * r;
    }
}

// ---------------------------------------------------------------------------
// conversions
// ---------------------------------------------------------------------------
__global__ __launch_bounds__(256) void cvt16_kernel(
    const float* __restrict__ in, __half* __restrict__ out, size_t n4)
{
    size_t i = (size_t)blockIdx.x * 256 + threadIdx.x;
    if (i >= n4) return;
    float4 v = reinterpret_cast<const float4*>(in)[i];
    ushort4 p;
    p.x = __half_as_ushort(__float2half_rn(v.x));
    p.y = __half_as_ushort(__float2half_rn(v.y));
    p.z = __half_as_ushort(__float2half_rn(v.z));
    p.w = __half_as_ushort(__float2half_rn(v.w));
    reinterpret_cast<ushort4*>(out)[i] = p;
}

__global__ __launch_bounds__(256) void cvt_wqkv_perm(
    const float* __restrict__ W, const float* __restrict__ bias,
    __half* __restrict__ Wp, float* __restrict__ biasp)
{
    const int idx = blockIdx.x * 256 + threadIdx.x;
    const int rp = idx >> 7;
    const int k4 = (idx & 127) * 4;
    const int head = rp / 192, rem = rp % 192, sec = rem / 64, d = rem % 64;
    const int ro = sec * H_DIM + head * HDIM + d;

    float4 v = *reinterpret_cast<const float4*>(W + (size_t)ro * GK + k4);
    ushort4 p;
    p.x = __half_as_ushort(__float2half_rn(v.x));
    p.y = __half_as_ushort(__float2half_rn(v.y));
    p.z = __half_as_ushort(__float2half_rn(v.z));
    p.w = __half_as_ushort(__float2half_rn(v.w));
    *reinterpret_cast<ushort4*>(Wp + (size_t)rp * GK + k4) = p;
    if ((idx & 127) == 0) biasp[rp] = bias[ro];
}

// ---------------------------------------------------------------------------
extern "C" void kernel_launch(void* const* d_in, const int* in_sizes, int n_in,
                              void* d_out, int out_size)
{
    const float* x    = (const float*)d_in[0];
    const float* W_fc = (const float*)d_in[1];
    const float* b_fc = (const float*)d_in[2];
    const float* ln_g = (const float*)d_in[3];
    const float* ln_b = (const float*)d_in[4];
    const float* Wqkv = (const float*)d_in[5];
    const float* bqkv = (const float*)d_in[6];
    const float* Wo   = (const float*)d_in[7];
    const float* bo   = (const float*)d_in[8];
    const float* gum  = (const float*)d_in[9];
    float* out = (float*)d_out;

    __half *abuf, *ctxbuf, *x16, *wfc, *wqkv, *wo;
    float* bqkvp;
    cudaGetSymbolAddress((void**)&abuf,   g_a);
    cudaGetSymbolAddress((void**)&ctxbuf, g_ctx);
    cudaGetSymbolAddress((void**)&x16,    g_x16);
    cudaGetSymbolAddress((void**)&wfc,    g_wfc);
    cudaGetSymbolAddress((void**)&wqkv,   g_wqkv);
    cudaGetSymbolAddress((void**)&bqkvp,  g_bqkv);
    cudaGetSymbolAddress((void**)&wo,     g_wo);

    cudaFuncSetAttribute(gemm_f16,
                         cudaFuncAttributeMaxDynamicSharedMemorySize, G1_SMEM);
    cudaFuncSetAttribute(gemm_ln_qkv_attn,
                         cudaFuncAttributeMaxDynamicSharedMemorySize, G2_SMEM);
    cudaFuncSetAttribute(gemm_out_gumbel,
                         cudaFuncAttributeMaxDynamicSharedMemorySize, G3_SMEM);

    dim3 blk(256);

    // 0) conversions
    {
        size_t n4;
        n4 = (size_t)B_SZ * IN_D / 4;
        cvt16_kernel<<<(unsigned)((n4 + 255) / 256), blk>>>(x, x16, n4);
        n4 = (size_t)H3 * IN_D / 4;
        cvt16_kernel<<<(unsigned)((n4 + 255) / 256), blk>>>(W_fc, wfc, n4);
        n4 = (size_t)H_DIM * H_DIM / 4;
        cvt16_kernel<<<(unsigned)((n4 + 255) / 256), blk>>>(Wo, wo, n4);
        cvt_wqkv_perm<<<(H3 * 128) / 256, blk>>>(Wqkv, bqkv, wqkv, bqkvp);
    }

    // 1) h = x @ W_fc^T + b_fc  [B,1536] fp16 (raw, pre-LN)
    gemm_f16<<<dim3(H3 / G1_BN, B_SZ / G1_BM), 512, G1_SMEM>>>(
        x16, wfc, b_fc, abuf, H3);

    // 2) LN+ReLU + qkv GEMM + attention fused -> ctx [3B,512]
    gemm_ln_qkv_attn<<<(3 * B_SZ) / 96, G2_THREADS, G2_SMEM>>>(
        abuf, wqkv, bqkvp, ln_g, ln_b, ctxbuf);

    // 3) output GEMM + gumbel fused -> out (3 slabs fp32)
    gemm_out_gumbel<<<dim3(H_DIM / G3_BN, (3 * B_SZ) / G3_BM), blk, G3_SMEM>>>(
        ctxbuf, wo, bo, gum, out);
}